// round 4
// baseline (speedup 1.0000x reference)
#include <cuda_runtime.h>
#include <cuda_bf16.h>

#define BB 64
#define SS 2048
#define RR 1024
#define HH 512
#define NSPLIT 8
#define SCHUNK (SS / NSPLIT)   // 256

// Scratch (allocation-free rule: __device__ globals)
__device__ float g_att_h[BB * HH];          // 128 KB
__device__ float g_weight[BB * SS];         // 512 KB (scores, then weights in-place)
__device__ float g_partial[NSPLIT * BB * RR]; // 2 MB

// ---------------------------------------------------------------------------
// K1: att_h[b,j] = dot(h[b,:], W[j,:]) + bias[j]
// grid (B, 64), block 256 (8 warps, one output j per warp)
// ---------------------------------------------------------------------------
__global__ void k1_att_h(const float* __restrict__ h,
                         const float* __restrict__ W,
                         const float* __restrict__ bias) {
    const int b    = blockIdx.x;
    const int warp = threadIdx.x >> 5;
    const int lane = threadIdx.x & 31;

    __shared__ float sh[RR];
    for (int i = threadIdx.x; i < RR / 4; i += blockDim.x)
        ((float4*)sh)[i] = ((const float4*)(h + (size_t)b * RR))[i];
    __syncthreads();

    const int j = blockIdx.y * 8 + warp;
    const float4* Wr = (const float4*)(W + (size_t)j * RR);

    float acc = 0.f;
#pragma unroll
    for (int i = 0; i < RR / 128; i++) {           // 8 iterations
        float4 w4 = Wr[i * 32 + lane];
        int k = (i * 32 + lane) * 4;
        acc += w4.x * sh[k] + w4.y * sh[k + 1] + w4.z * sh[k + 2] + w4.w * sh[k + 3];
    }
#pragma unroll
    for (int o = 16; o; o >>= 1) acc += __shfl_down_sync(0xFFFFFFFFu, acc, o);
    if (lane == 0) g_att_h[b * HH + j] = acc + bias[j];
}

// ---------------------------------------------------------------------------
// K2: scores[b,s] = sum_h tanh(p[b,s,h] + att_h[b,h]) * w_alpha[h] + b_alpha
// grid (B, S/8), block 256 (8 warps, one s per warp). 256 MB streaming read.
// ---------------------------------------------------------------------------
__global__ void k2_scores(const float* __restrict__ p,
                          const float* __restrict__ w_alpha,
                          const float* __restrict__ b_alpha) {
    const int b = blockIdx.x;

    __shared__ float s_ah[HH];
    __shared__ float s_wa[HH];
    for (int i = threadIdx.x; i < HH / 4; i += blockDim.x) {
        ((float4*)s_ah)[i] = ((const float4*)(g_att_h + (size_t)b * HH))[i];
        ((float4*)s_wa)[i] = ((const float4*)w_alpha)[i];
    }
    __syncthreads();

    const int warp = threadIdx.x >> 5;
    const int lane = threadIdx.x & 31;
    const int s    = blockIdx.y * 8 + warp;

    const float4* pr = (const float4*)(p + ((size_t)b * SS + s) * HH);

    float acc = 0.f;
#pragma unroll
    for (int i = 0; i < HH / 128; i++) {           // 4 iterations
        float4 p4 = pr[i * 32 + lane];
        int k = (i * 32 + lane) * 4;
        acc += tanhf(p4.x + s_ah[k])     * s_wa[k];
        acc += tanhf(p4.y + s_ah[k + 1]) * s_wa[k + 1];
        acc += tanhf(p4.z + s_ah[k + 2]) * s_wa[k + 2];
        acc += tanhf(p4.w + s_ah[k + 3]) * s_wa[k + 3];
    }
#pragma unroll
    for (int o = 16; o; o >>= 1) acc += __shfl_down_sync(0xFFFFFFFFu, acc, o);
    if (lane == 0) g_weight[b * SS + s] = acc + b_alpha[0];
}

// ---------------------------------------------------------------------------
// K3: masked softmax per batch row. softmax -> *mask -> renorm is algebraically
// e_i*m_i / sum_j(e_j*m_j) with a shared max subtraction.
// grid B, block 1024 (each thread owns 2 elements).
// ---------------------------------------------------------------------------
__global__ void k3_softmax(const int* __restrict__ mask) {
    const int b   = blockIdx.x;
    const int tid = threadIdx.x;

    float v0 = g_weight[b * SS + tid];
    float v1 = g_weight[b * SS + tid + 1024];

    __shared__ float red_max[32];
    __shared__ float red_sum[32];

    // global max (over ALL scores, as reference does)
    float mx = fmaxf(v0, v1);
#pragma unroll
    for (int o = 16; o; o >>= 1) mx = fmaxf(mx, __shfl_xor_sync(0xFFFFFFFFu, mx, o));
    if ((tid & 31) == 0) red_max[tid >> 5] = mx;
    __syncthreads();
    if (tid < 32) {
        float m = red_max[tid];
#pragma unroll
        for (int o = 16; o; o >>= 1) m = fmaxf(m, __shfl_xor_sync(0xFFFFFFFFu, m, o));
        red_max[tid] = m;
    }
    __syncthreads();
    mx = red_max[0];

    const int m0 = mask[b * SS + tid];
    const int m1 = mask[b * SS + tid + 1024];
    float e0 = m0 ? expf(v0 - mx) : 0.f;
    float e1 = m1 ? expf(v1 - mx) : 0.f;

    float sum = e0 + e1;
#pragma unroll
    for (int o = 16; o; o >>= 1) sum += __shfl_xor_sync(0xFFFFFFFFu, sum, o);
    if ((tid & 31) == 0) red_sum[tid >> 5] = sum;
    __syncthreads();
    if (tid < 32) {
        float s = red_sum[tid];
#pragma unroll
        for (int o = 16; o; o >>= 1) s += __shfl_xor_sync(0xFFFFFFFFu, s, o);
        red_sum[tid] = s;
    }
    __syncthreads();
    const float inv = 1.f / red_sum[0];

    g_weight[b * SS + tid]        = e0 * inv;
    g_weight[b * SS + tid + 1024] = e1 * inv;
}

// ---------------------------------------------------------------------------
// K4: partial weighted sums over an S-chunk.
// grid (B, NSPLIT), block 256. Each thread owns 4 R-columns (float4); block
// covers the full R=1024 row; loops over 256 s-steps. 512 MB streaming read.
// ---------------------------------------------------------------------------
__global__ void k4_wsum(const float* __restrict__ feats) {
    const int b  = blockIdx.x;
    const int sp = blockIdx.y;
    const int s0 = sp * SCHUNK;

    __shared__ float sw[SCHUNK];
    for (int i = threadIdx.x; i < SCHUNK; i += blockDim.x)
        sw[i] = g_weight[b * SS + s0 + i];
    __syncthreads();

    const float4* base = (const float4*)(feats + ((size_t)b * SS + s0) * RR) + threadIdx.x;

    float4 acc = make_float4(0.f, 0.f, 0.f, 0.f);
#pragma unroll 4
    for (int i = 0; i < SCHUNK; i++) {
        float4 f = base[(size_t)i * (RR / 4)];
        float w = sw[i];
        acc.x += w * f.x; acc.y += w * f.y; acc.z += w * f.z; acc.w += w * f.w;
    }
    ((float4*)(g_partial + ((size_t)sp * BB + b) * RR))[threadIdx.x] = acc;
}

// ---------------------------------------------------------------------------
// K5: reduce NSPLIT partials into the output. grid 64, block 256, float4/thread.
// ---------------------------------------------------------------------------
__global__ void k5_reduce(float* __restrict__ out) {
    const int idx = blockIdx.x * 256 + threadIdx.x;   // float4 index into [B*R/4]
    float4 acc = make_float4(0.f, 0.f, 0.f, 0.f);
#pragma unroll
    for (int sp = 0; sp < NSPLIT; sp++) {
        float4 f = ((const float4*)(g_partial + (size_t)sp * BB * RR))[idx];
        acc.x += f.x; acc.y += f.y; acc.z += f.z; acc.w += f.w;
    }
    ((float4*)out)[idx] = acc;
}

// ---------------------------------------------------------------------------
extern "C" void kernel_launch(void* const* d_in, const int* in_sizes, int n_in,
                              void* d_out, int out_size) {
    const float* h         = (const float*)d_in[0];
    const float* att_feats = (const float*)d_in[1];
    const float* p_att     = (const float*)d_in[2];
    const int*   masks     = (const int*)  d_in[3];
    const float* W         = (const float*)d_in[4];
    const float* b_h2att   = (const float*)d_in[5];
    const float* w_alpha   = (const float*)d_in[6];
    const float* b_alpha   = (const float*)d_in[7];
    float*       out       = (float*)d_out;

    k1_att_h  <<<dim3(BB, HH / 8),  256>>>(h, W, b_h2att);
    k2_scores <<<dim3(BB, SS / 8),  256>>>(p_att, w_alpha, b_alpha);
    k3_softmax<<<BB,               1024>>>(masks);
    k4_wsum   <<<dim3(BB, NSPLIT),  256>>>(att_feats);
    k5_reduce <<<BB * RR / 1024,    256>>>(out);
}

// round 5
// speedup vs baseline: 1.1295x; 1.1295x over previous
#include <cuda_runtime.h>
#include <cuda_bf16.h>

#define BB 64
#define SS 2048
#define RR 1024
#define HH 512
#define NSPLIT 8
#define SCHUNK (SS / NSPLIT)   // 256

// Scratch (allocation-free rule: __device__ globals)
__device__ float g_att_h[BB * HH];            // 128 KB
__device__ float g_score[BB * SS];            // 512 KB (raw scores; softmax fused into k4)
__device__ float g_partial[NSPLIT * BB * RR]; // 2 MB

__device__ __forceinline__ float fast_tanh(float x) {
    float y;
    asm("tanh.approx.f32 %0, %1;" : "=f"(y) : "f"(x));
    return y;
}

// ---------------------------------------------------------------------------
// K1: att_h[b,j] = dot(h[b,:], W[j,:]) + bias[j]
// grid (B, 64), block 256 (8 warps, one output j per warp)
// ---------------------------------------------------------------------------
__global__ void k1_att_h(const float* __restrict__ h,
                         const float* __restrict__ W,
                         const float* __restrict__ bias) {
    const int b    = blockIdx.x;
    const int warp = threadIdx.x >> 5;
    const int lane = threadIdx.x & 31;

    __shared__ float sh[RR];
    for (int i = threadIdx.x; i < RR / 4; i += blockDim.x)
        ((float4*)sh)[i] = ((const float4*)(h + (size_t)b * RR))[i];
    __syncthreads();

    const int j = blockIdx.y * 8 + warp;
    const float4* Wr = (const float4*)(W + (size_t)j * RR);

    float acc = 0.f;
#pragma unroll
    for (int i = 0; i < RR / 128; i++) {           // 8 iterations
        float4 w4 = Wr[i * 32 + lane];
        int k = (i * 32 + lane) * 4;
        acc += w4.x * sh[k] + w4.y * sh[k + 1] + w4.z * sh[k + 2] + w4.w * sh[k + 3];
    }
#pragma unroll
    for (int o = 16; o; o >>= 1) acc += __shfl_down_sync(0xFFFFFFFFu, acc, o);
    if (lane == 0) g_att_h[b * HH + j] = acc + bias[j];
}

// ---------------------------------------------------------------------------
// K2: score[b,s] = sum_h tanh(p[b,s,h] + att_h[b,h]) * w_alpha[h]
// (b_alpha dropped: a constant shift cancels in softmax)
// grid (B, S/8), block 256 (8 warps, one s per warp). 256 MB streaming read.
// tanh via MUFU.TANH so the kernel stays HBM-bound.
// ---------------------------------------------------------------------------
__global__ void k2_scores(const float* __restrict__ p,
                          const float* __restrict__ w_alpha) {
    const int b = blockIdx.x;

    __shared__ float s_ah[HH];
    __shared__ float s_wa[HH];
    for (int i = threadIdx.x; i < HH / 4; i += blockDim.x) {
        ((float4*)s_ah)[i] = ((const float4*)(g_att_h + (size_t)b * HH))[i];
        ((float4*)s_wa)[i] = ((const float4*)w_alpha)[i];
    }
    __syncthreads();

    const int warp = threadIdx.x >> 5;
    const int lane = threadIdx.x & 31;
    const int s    = blockIdx.y * 8 + warp;

    const float4* pr = (const float4*)(p + ((size_t)b * SS + s) * HH);

    float acc = 0.f;
#pragma unroll
    for (int i = 0; i < HH / 128; i++) {           // 4 iterations
        float4 p4 = pr[i * 32 + lane];
        int k = (i * 32 + lane) * 4;
        acc += fast_tanh(p4.x + s_ah[k])     * s_wa[k];
        acc += fast_tanh(p4.y + s_ah[k + 1]) * s_wa[k + 1];
        acc += fast_tanh(p4.z + s_ah[k + 2]) * s_wa[k + 2];
        acc += fast_tanh(p4.w + s_ah[k + 3]) * s_wa[k + 3];
    }
#pragma unroll
    for (int o = 16; o; o >>= 1) acc += __shfl_down_sync(0xFFFFFFFFu, acc, o);
    if (lane == 0) g_score[b * SS + s] = acc;
}

// ---------------------------------------------------------------------------
// K4: fused softmax + partial weighted sums over an S-chunk.
// grid (B, NSPLIT), block 256.
// Prologue: each block redundantly computes the batch row's masked softmax
// (16 KB of scores+mask, 2048 exp) and keeps its own 256 chunk weights in smem.
// softmax -> *mask -> renorm  ==  e_i*m_i / sum_j(e_j*m_j)  (max-subtracted).
// Main loop: 512 MB streaming read of att_feats.
// ---------------------------------------------------------------------------
__global__ void k4_wsum(const float* __restrict__ feats,
                        const int* __restrict__ mask) {
    const int b   = blockIdx.x;
    const int sp  = blockIdx.y;
    const int s0  = sp * SCHUNK;
    const int tid = threadIdx.x;

    __shared__ float sw[SCHUNK];
    __shared__ float red[8];

    // --- load all SS scores for this batch row: thread tid owns indices tid + k*256
    float v[NSPLIT];
    int   m[NSPLIT];
#pragma unroll
    for (int k = 0; k < NSPLIT; k++) {
        v[k] = g_score[b * SS + k * 256 + tid];
        m[k] = mask[b * SS + k * 256 + tid];
    }

    // --- block max (over all scores, matching reference stability)
    float mx = v[0];
#pragma unroll
    for (int k = 1; k < NSPLIT; k++) mx = fmaxf(mx, v[k]);
#pragma unroll
    for (int o = 16; o; o >>= 1) mx = fmaxf(mx, __shfl_xor_sync(0xFFFFFFFFu, mx, o));
    if ((tid & 31) == 0) red[tid >> 5] = mx;
    __syncthreads();
    mx = fmaxf(fmaxf(fmaxf(red[0], red[1]), fmaxf(red[2], red[3])),
               fmaxf(fmaxf(red[4], red[5]), fmaxf(red[6], red[7])));
    __syncthreads();

    // --- masked exponentials + block sum
    float e[NSPLIT];
    float sum = 0.f;
#pragma unroll
    for (int k = 0; k < NSPLIT; k++) {
        e[k] = m[k] ? __expf(v[k] - mx) : 0.f;
        sum += e[k];
    }
#pragma unroll
    for (int o = 16; o; o >>= 1) sum += __shfl_xor_sync(0xFFFFFFFFu, sum, o);
    if ((tid & 31) == 0) red[tid >> 5] = sum;
    __syncthreads();
    sum = red[0] + red[1] + red[2] + red[3] + red[4] + red[5] + red[6] + red[7];
    const float inv = 1.f / sum;

    // this block's chunk weights: chunk sp covers indices sp*256 + tid -> k == sp
    sw[tid] = e[sp] * inv;
    __syncthreads();

    // --- streaming weighted sum
    const float4* base = (const float4*)(feats + ((size_t)b * SS + s0) * RR) + tid;

    float4 acc = make_float4(0.f, 0.f, 0.f, 0.f);
#pragma unroll 4
    for (int i = 0; i < SCHUNK; i++) {
        float4 f = base[(size_t)i * (RR / 4)];
        float w = sw[i];
        acc.x += w * f.x; acc.y += w * f.y; acc.z += w * f.z; acc.w += w * f.w;
    }
    ((float4*)(g_partial + ((size_t)sp * BB + b) * RR))[tid] = acc;
}

// ---------------------------------------------------------------------------
// K5: reduce NSPLIT partials into the output. grid 64, block 256, float4/thread.
// ---------------------------------------------------------------------------
__global__ void k5_reduce(float* __restrict__ out) {
    const int idx = blockIdx.x * 256 + threadIdx.x;   // float4 index into [B*R/4]
    float4 acc = make_float4(0.f, 0.f, 0.f, 0.f);
#pragma unroll
    for (int sp = 0; sp < NSPLIT; sp++) {
        float4 f = ((const float4*)(g_partial + (size_t)sp * BB * RR))[idx];
        acc.x += f.x; acc.y += f.y; acc.z += f.z; acc.w += f.w;
    }
    ((float4*)out)[idx] = acc;
}

// ---------------------------------------------------------------------------
extern "C" void kernel_launch(void* const* d_in, const int* in_sizes, int n_in,
                              void* d_out, int out_size) {
    const float* h         = (const float*)d_in[0];
    const float* att_feats = (const float*)d_in[1];
    const float* p_att     = (const float*)d_in[2];
    const int*   masks     = (const int*)  d_in[3];
    const float* W         = (const float*)d_in[4];
    const float* b_h2att   = (const float*)d_in[5];
    const float* w_alpha   = (const float*)d_in[6];
    // d_in[7] = b_alpha: unused (constant shift cancels in softmax)
    float*       out       = (float*)d_out;

    k1_att_h  <<<dim3(BB, HH / 8), 256>>>(h, W, b_h2att);
    k2_scores <<<dim3(BB, SS / 8), 256>>>(p_att, w_alpha);
    k4_wsum   <<<dim3(BB, NSPLIT), 256>>>(att_feats, masks);
    k5_reduce <<<BB * RR / 1024,   256>>>(out);
}

// round 6
// speedup vs baseline: 1.1344x; 1.0043x over previous
#include <cuda_runtime.h>
#include <cuda_bf16.h>

#define BB 64
#define SS 2048
#define RR 1024
#define HH 512
#define NSPLIT 8
#define SCHUNK (SS / NSPLIT)   // 256

// Scratch (allocation-free rule: __device__ globals)
__device__ float g_att_h[BB * HH];            // 128 KB
__device__ float g_score[BB * SS];            // 512 KB (raw scores; softmax fused into k4)
__device__ float g_partial[NSPLIT * BB * RR]; // 2 MB

__device__ __forceinline__ float fast_tanh(float x) {
    float y;
    asm("tanh.approx.f32 %0, %1;" : "=f"(y) : "f"(x));
    return y;
}

// ---------------------------------------------------------------------------
// K1: att_h[b,j] = dot(h[b,:], W[j,:]) + bias[j]
// grid (B, 64), block 256 (8 warps, one output j per warp)
// ---------------------------------------------------------------------------
__global__ void k1_att_h(const float* __restrict__ h,
                         const float* __restrict__ W,
                         const float* __restrict__ bias) {
    const int b    = blockIdx.x;
    const int warp = threadIdx.x >> 5;
    const int lane = threadIdx.x & 31;

    __shared__ float sh[RR];
    for (int i = threadIdx.x; i < RR / 4; i += blockDim.x)
        ((float4*)sh)[i] = ((const float4*)(h + (size_t)b * RR))[i];
    __syncthreads();

    const int j = blockIdx.y * 8 + warp;
    const float4* Wr = (const float4*)(W + (size_t)j * RR);

    float acc = 0.f;
#pragma unroll
    for (int i = 0; i < RR / 128; i++) {           // 8 iterations
        float4 w4 = Wr[i * 32 + lane];
        int k = (i * 32 + lane) * 4;
        acc += w4.x * sh[k] + w4.y * sh[k + 1] + w4.z * sh[k + 2] + w4.w * sh[k + 3];
    }
#pragma unroll
    for (int o = 16; o; o >>= 1) acc += __shfl_down_sync(0xFFFFFFFFu, acc, o);
    if (lane == 0) g_att_h[b * HH + j] = acc + bias[j];
}

// ---------------------------------------------------------------------------
// K2: score[b,s] = sum_h tanh(p[b,s,h] + att_h[b,h]) * w_alpha[h]
// (b_alpha dropped: a constant shift cancels in softmax)
// grid (B, S/8), block 256 (8 warps, one s per warp). 256 MB streaming read.
// tanh via MUFU.TANH so the kernel stays HBM-bound.
// ---------------------------------------------------------------------------
__global__ void k2_scores(const float* __restrict__ p,
                          const float* __restrict__ w_alpha) {
    const int b = blockIdx.x;

    __shared__ float s_ah[HH];
    __shared__ float s_wa[HH];
    for (int i = threadIdx.x; i < HH / 4; i += blockDim.x) {
        ((float4*)s_ah)[i] = ((const float4*)(g_att_h + (size_t)b * HH))[i];
        ((float4*)s_wa)[i] = ((const float4*)w_alpha)[i];
    }
    __syncthreads();

    const int warp = threadIdx.x >> 5;
    const int lane = threadIdx.x & 31;
    const int s    = blockIdx.y * 8 + warp;

    const float4* pr = (const float4*)(p + ((size_t)b * SS + s) * HH);

    float acc = 0.f;
#pragma unroll
    for (int i = 0; i < HH / 128; i++) {           // 4 iterations
        float4 p4 = pr[i * 32 + lane];
        int k = (i * 32 + lane) * 4;
        acc += fast_tanh(p4.x + s_ah[k])     * s_wa[k];
        acc += fast_tanh(p4.y + s_ah[k + 1]) * s_wa[k + 1];
        acc += fast_tanh(p4.z + s_ah[k + 2]) * s_wa[k + 2];
        acc += fast_tanh(p4.w + s_ah[k + 3]) * s_wa[k + 3];
    }
#pragma unroll
    for (int o = 16; o; o >>= 1) acc += __shfl_down_sync(0xFFFFFFFFu, acc, o);
    if (lane == 0) g_score[b * SS + s] = acc;
}

// ---------------------------------------------------------------------------
// K4: fused softmax + partial weighted sums over an S-chunk.
// grid (B, NSPLIT), block 256.
// Prologue: each block redundantly computes the batch row's masked softmax
// (16 KB of scores+mask, 2048 exp) and keeps its own 256 chunk weights in smem.
// softmax -> *mask -> renorm  ==  e_i*m_i / sum_j(e_j*m_j)  (max-subtracted).
// Main loop: 512 MB streaming read of att_feats.
// ---------------------------------------------------------------------------
__global__ void k4_wsum(const float* __restrict__ feats,
                        const int* __restrict__ mask) {
    const int b   = blockIdx.x;
    const int sp  = blockIdx.y;
    const int s0  = sp * SCHUNK;
    const int tid = threadIdx.x;

    __shared__ float sw[SCHUNK];
    __shared__ float red[8];

    // --- load all SS scores for this batch row: thread tid owns indices tid + k*256
    float v[NSPLIT];
    int   m[NSPLIT];
#pragma unroll
    for (int k = 0; k < NSPLIT; k++) {
        v[k] = g_score[b * SS + k * 256 + tid];
        m[k] = mask[b * SS + k * 256 + tid];
    }

    // --- block max (over all scores, matching reference stability)
    float mx = v[0];
#pragma unroll
    for (int k = 1; k < NSPLIT; k++) mx = fmaxf(mx, v[k]);
#pragma unroll
    for (int o = 16; o; o >>= 1) mx = fmaxf(mx, __shfl_xor_sync(0xFFFFFFFFu, mx, o));
    if ((tid & 31) == 0) red[tid >> 5] = mx;
    __syncthreads();
    mx = fmaxf(fmaxf(fmaxf(red[0], red[1]), fmaxf(red[2], red[3])),
               fmaxf(fmaxf(red[4], red[5]), fmaxf(red[6], red[7])));
    __syncthreads();

    // --- masked exponentials + block sum
    float e[NSPLIT];
    float sum = 0.f;
#pragma unroll
    for (int k = 0; k < NSPLIT; k++) {
        e[k] = m[k] ? __expf(v[k] - mx) : 0.f;
        sum += e[k];
    }
#pragma unroll
    for (int o = 16; o; o >>= 1) sum += __shfl_xor_sync(0xFFFFFFFFu, sum, o);
    if ((tid & 31) == 0) red[tid >> 5] = sum;
    __syncthreads();
    sum = red[0] + red[1] + red[2] + red[3] + red[4] + red[5] + red[6] + red[7];
    const float inv = 1.f / sum;

    // this block's chunk weights: chunk sp covers indices sp*256 + tid -> k == sp
    sw[tid] = e[sp] * inv;
    __syncthreads();

    // --- streaming weighted sum
    const float4* base = (const float4*)(feats + ((size_t)b * SS + s0) * RR) + tid;

    float4 acc = make_float4(0.f, 0.f, 0.f, 0.f);
#pragma unroll 4
    for (int i = 0; i < SCHUNK; i++) {
        float4 f = base[(size_t)i * (RR / 4)];
        float w = sw[i];
        acc.x += w * f.x; acc.y += w * f.y; acc.z += w * f.z; acc.w += w * f.w;
    }
    ((float4*)(g_partial + ((size_t)sp * BB + b) * RR))[tid] = acc;
}

// ---------------------------------------------------------------------------
// K5: reduce NSPLIT partials into the output. grid 64, block 256, float4/thread.
// ---------------------------------------------------------------------------
__global__ void k5_reduce(float* __restrict__ out) {
    const int idx = blockIdx.x * 256 + threadIdx.x;   // float4 index into [B*R/4]
    float4 acc = make_float4(0.f, 0.f, 0.f, 0.f);
#pragma unroll
    for (int sp = 0; sp < NSPLIT; sp++) {
        float4 f = ((const float4*)(g_partial + (size_t)sp * BB * RR))[idx];
        acc.x += f.x; acc.y += f.y; acc.z += f.z; acc.w += f.w;
    }
    ((float4*)out)[idx] = acc;
}

// ---------------------------------------------------------------------------
extern "C" void kernel_launch(void* const* d_in, const int* in_sizes, int n_in,
                              void* d_out, int out_size) {
    const float* h         = (const float*)d_in[0];
    const float* att_feats = (const float*)d_in[1];
    const float* p_att     = (const float*)d_in[2];
    const int*   masks     = (const int*)  d_in[3];
    const float* W         = (const float*)d_in[4];
    const float* b_h2att   = (const float*)d_in[5];
    const float* w_alpha   = (const float*)d_in[6];
    // d_in[7] = b_alpha: unused (constant shift cancels in softmax)
    float*       out       = (float*)d_out;

    k1_att_h  <<<dim3(BB, HH / 8), 256>>>(h, W, b_h2att);
    k2_scores <<<dim3(BB, SS / 8), 256>>>(p_att, w_alpha);
    k4_wsum   <<<dim3(BB, NSPLIT), 256>>>(att_feats, masks);
    k5_reduce <<<BB * RR / 1024,   256>>>(out);
}